// round 3
// baseline (speedup 1.0000x reference)
#include <cuda_runtime.h>
#include <math.h>

#define BB 8
#define CC 64
#define TT 24
#define NN 512
#define HH 2
#define HD 32
#define BT (BB*TT)

// ---------------- scratch (static device globals; no allocation) ----------------
__device__ float g_V[BT*NN*CC];      // V per (bt, n, c)
__device__ float g_O[BT*NN*CC];      // attention output pre-LN
__device__ float g_ssrc[BT*HH*NN];
__device__ float g_psrc[BT*HH*NN];
__device__ float g_qsrc[BT*HH*NN];
__device__ float g_sdst[BT*HH*NN];
__device__ float g_pdst[BT*HH*NN];
__device__ float g_qdst[BT*HH*NN];
__device__ float g_wqa[HH*CC];
__device__ float g_wka[HH*CC];
__device__ unsigned g_mask[NN*16];   // packed gso bits, row-major

// ---------------- kernel A: fold a_src/a_dst into Wq/Wk; pack mask ----------------
__global__ void prep_kernel(const float* __restrict__ Wq, const float* __restrict__ Wk,
                            const float* __restrict__ a_src, const float* __restrict__ a_dst,
                            const int* __restrict__ gso) {
    int t = threadIdx.x;
    if (t < 128) {
        int h = t >> 6, c = t & 63;
        float s1 = 0.f, s2 = 0.f;
        for (int d = 0; d < HD; d++) {
            s1 += Wq[(h*HD + d)*CC + c] * a_src[h*HD + d];
            s2 += Wk[(h*HD + d)*CC + c] * a_dst[h*HD + d];
        }
        g_wqa[t] = s1;
        g_wka[t] = s2;
    }
    for (int w = t; w < NN*16; w += 256) {
        int r = w >> 4, wi = w & 15;
        const int* row = gso + r*NN + wi*32;
        unsigned bits = 0;
        #pragma unroll
        for (int b = 0; b < 32; b++) bits |= (row[b] != 0) ? (1u << b) : 0u;
        g_mask[w] = bits;
    }
}

// ---------------- kernel B: fused transpose + V projection + scores ----------------
__global__ __launch_bounds__(256) void qkv_kernel(const float* __restrict__ x,
                                                  const float* __restrict__ Wv) {
    __shared__ float sWv[CC*CC];
    __shared__ float swqa[HH*CC], swka[HH*CC];
    int tid = threadIdx.x;
    for (int e = tid; e < CC*CC; e += 256) sWv[e] = Wv[e];
    if (tid < 128) { swqa[tid] = g_wqa[tid]; swka[tid] = g_wka[tid]; }
    __syncthreads();

    int bt = blockIdx.x;
    int n  = blockIdx.y*256 + tid;
    int b = bt / TT, tim = bt % TT;
    const float* xp = x + (b*CC*TT + tim)*NN + n;   // + c*TT*NN strides

    float xv[CC];
    #pragma unroll
    for (int c = 0; c < CC; c++) xv[c] = xp[c*TT*NN];

    #pragma unroll
    for (int h = 0; h < HH; h++) {
        float s1 = 0.f, s2 = 0.f;
        #pragma unroll
        for (int c = 0; c < CC; c++) { s1 += xv[c]*swqa[h*CC+c]; s2 += xv[c]*swka[h*CC+c]; }
        int o = (bt*HH + h)*NN + n;
        g_ssrc[o] = s1; g_psrc[o] = expf(s1); g_qsrc[o] = expf(0.2f*s1);
        g_sdst[o] = s2; g_pdst[o] = expf(s2); g_qdst[o] = expf(0.2f*s2);
    }

    float* vp = g_V + (bt*NN + n)*CC;
    #pragma unroll
    for (int dg = 0; dg < 16; dg++) {
        float a0=0.f, a1=0.f, a2=0.f, a3=0.f;
        #pragma unroll
        for (int c = 0; c < CC; c++) {
            float xc = xv[c];
            a0 += xc*sWv[(dg*4+0)*CC + c];
            a1 += xc*sWv[(dg*4+1)*CC + c];
            a2 += xc*sWv[(dg*4+2)*CC + c];
            a3 += xc*sWv[(dg*4+3)*CC + c];
        }
        *(float4*)(vp + dg*4) = make_float4(a0, a1, a2, a3);
    }
}

// ---------------- kernel C: attention (W-tile build + AV matmul) ----------------
// grid (bt=192, h=2, ihalf=2); block 256. Dynamic smem layout in floats:
#define OFF_V   0        // 512*32
#define OFF_W   16384    // 64*64
#define OFF_SD  20480
#define OFF_PD  20992
#define OFF_QD  21504
#define OFF_SS  22016
#define OFF_PS  22272
#define OFF_QS  22528
#define OFF_ZP  22784    // 64*4
#define OFF_Z   23040    // 64
#define OFF_M   23104    // 256*17 uints (padded rows vs bank conflicts)
#define ATTN_SMEM_FLOATS (23104 + 256*17)
#define ATTN_SMEM_BYTES  (ATTN_SMEM_FLOATS*4)

__global__ __launch_bounds__(256) void attn_kernel() {
    extern __shared__ float sm[];
    float4*  sV4 = (float4*)sm;
    float*   sW  = sm + OFF_W;
    float*   sSd = sm + OFF_SD;
    float*   sPd = sm + OFF_PD;
    float*   sQd = sm + OFF_QD;
    float*   sSs = sm + OFF_SS;
    float*   sPs = sm + OFF_PS;
    float*   sQs = sm + OFF_QS;
    float*   sZp = sm + OFF_ZP;
    float*   sZ  = sm + OFF_Z;
    unsigned* sM = (unsigned*)(sm + OFF_M);

    int bt = blockIdx.x, h = blockIdx.y, ihalf = blockIdx.z;
    int tid = threadIdx.x;

    // load this head's V: [512][32] floats
    const float4* gV4 = (const float4*)(g_V + (bt*NN)*CC + h*HD);
    for (int e = tid; e < 4096; e += 256) {
        int j = e >> 3, q = e & 7;
        sV4[e] = gV4[j*16 + q];       // global row stride = 64 floats = 16 float4
    }
    int base = (bt*HH + h)*NN;
    for (int e = tid; e < NN; e += 256) {
        sSd[e] = g_sdst[base+e]; sPd[e] = g_pdst[base+e]; sQd[e] = g_qdst[base+e];
    }
    {
        int ib2 = base + ihalf*256;
        sSs[tid] = g_ssrc[ib2+tid]; sPs[tid] = g_psrc[ib2+tid]; sQs[tid] = g_qsrc[ib2+tid];
    }
    for (int e = tid; e < 4096; e += 256) {
        int r = e >> 4, wi = e & 15;
        sM[r*17 + wi] = g_mask[(ihalf*256 + r)*16 + wi];
    }
    __syncthreads();

    int warp = tid >> 5, lane = tid & 31;
    int i_sub = lane & 7, dq = lane >> 3;
    int iw = warp*8 + i_sub;             // matmul role: i within 64-block
    int bi = tid & 63, jc = tid >> 6;    // builder role

    for (int ib = 0; ib < 4; ib++) {
        float si = sSs[ib*64 + bi], pi = sPs[ib*64 + bi], qi = sQs[ib*64 + bi];
        int mrow = (ib*64 + bi)*17;
        float z = 0.f;
        float a0=0.f,a1=0.f,a2=0.f,a3=0.f,a4=0.f,a5=0.f,a6=0.f,a7=0.f;

        for (int jt = 0; jt < 8; jt++) {
            // ---- build W tile [64 j][64 i] (each w computed exactly once) ----
            unsigned mword = sM[mrow + jt*2 + (jc >> 1)] >> ((jc & 1)*16);
            int j0 = jt*64 + jc*16;
            float* wdst = sW + jc*16*64 + bi;
            #pragma unroll
            for (int s = 0; s < 16; s++) {
                int j = j0 + s;
                float t = si + sSd[j];
                float w = (t > 0.f) ? pi*sPd[j] : qi*sQd[j];
                w = ((mword >> s) & 1u) ? w : 0.f;
                wdst[s*64] = w;          // coalesced STS across lanes
                z += w;
            }
            __syncthreads();
            // ---- matmul: warp covers 8 i x 32 d; lane = (i_sub, dq) ----
            const float4* vb = sV4 + jt*64*8 + dq*2;
            const float*  wb = sW + iw;
            #pragma unroll 8
            for (int j = 0; j < 64; j++) {
                float w  = wb[j*64];        // 8 distinct scalars, multicast
                float4 v0 = vb[j*8];
                float4 v1 = vb[j*8 + 1];
                a0 += w*v0.x; a1 += w*v0.y; a2 += w*v0.z; a3 += w*v0.w;
                a4 += w*v1.x; a5 += w*v1.y; a6 += w*v1.z; a7 += w*v1.w;
            }
            __syncthreads();
        }
        // ---- softmax normalizer ----
        sZp[bi*4 + jc] = z;
        __syncthreads();
        if (tid < 64) sZ[tid] = sZp[tid*4] + sZp[tid*4+1] + sZp[tid*4+2] + sZp[tid*4+3];
        __syncthreads();
        float rz = 1.f / sZ[iw];
        int ig = ihalf*256 + ib*64 + iw;
        float* op = g_O + (bt*NN + ig)*CC + h*HD + dq*8;
        ((float4*)op)[0] = make_float4(a0*rz, a1*rz, a2*rz, a3*rz);
        ((float4*)op)[1] = make_float4(a4*rz, a5*rz, a6*rz, a7*rz);
        __syncthreads();
    }
}

// ---------------- kernel D: LayerNorm over C + transposed writeout ----------------
__global__ __launch_bounds__(256) void ln_kernel(const float* __restrict__ gamma,
                                                 const float* __restrict__ beta,
                                                 float* __restrict__ y) {
    __shared__ float smb[32*65];
    __shared__ float sg[64], sb[64];
    int tid = threadIdx.x;
    int bt = blockIdx.x, nt = blockIdx.y;
    if (tid < 64) { sg[tid] = gamma[tid]; sb[tid] = beta[tid]; }
    const float* o = g_O + (bt*NN + nt*32)*CC;
    for (int e = tid; e < 2048; e += 256)
        smb[(e >> 6)*65 + (e & 63)] = o[e];
    __syncthreads();

    int warp = tid >> 5, lane = tid & 31;
    #pragma unroll
    for (int k = 0; k < 4; k++) {
        int r = warp*4 + k;
        float v0 = smb[r*65 + lane], v1 = smb[r*65 + 32 + lane];
        float s = v0 + v1, ss2 = v0*v0 + v1*v1;
        #pragma unroll
        for (int off = 16; off; off >>= 1) {
            s   += __shfl_xor_sync(0xffffffffu, s, off);
            ss2 += __shfl_xor_sync(0xffffffffu, ss2, off);
        }
        float mu  = s*(1.f/64.f);
        float var = ss2*(1.f/64.f) - mu*mu;
        float rs  = rsqrtf(var + 1e-5f);
        smb[r*65 + lane]      = (v0 - mu)*rs*sg[lane]      + sb[lane];
        smb[r*65 + 32 + lane] = (v1 - mu)*rs*sg[32 + lane] + sb[32 + lane];
    }
    __syncthreads();

    int b = bt / TT, tim = bt % TT;
    int n = tid & 31, c0 = tid >> 5;
    float* yp = y + (b*CC*TT + tim)*NN + nt*32 + n;
    #pragma unroll
    for (int k = 0; k < 8; k++) {
        int c = c0 + k*8;
        yp[c*TT*NN] = smb[n*65 + c];   // warp writes 32 consecutive n: coalesced
    }
}

// ---------------- launch ----------------
extern "C" void kernel_launch(void* const* d_in, const int* in_sizes, int n_in,
                              void* d_out, int out_size) {
    const float* x     = (const float*)d_in[0];
    const int*   gso   = (const int*)  d_in[1];
    const float* Wq    = (const float*)d_in[2];
    const float* Wk    = (const float*)d_in[3];
    const float* Wv    = (const float*)d_in[4];
    const float* a_src = (const float*)d_in[5];
    const float* a_dst = (const float*)d_in[6];
    const float* gam   = (const float*)d_in[7];
    const float* bet   = (const float*)d_in[8];
    float* y = (float*)d_out;

    cudaFuncSetAttribute(attn_kernel, cudaFuncAttributeMaxDynamicSharedMemorySize,
                         ATTN_SMEM_BYTES);

    prep_kernel<<<1, 256>>>(Wq, Wk, a_src, a_dst, gso);
    qkv_kernel<<<dim3(BT, 2), 256>>>(x, Wv);
    attn_kernel<<<dim3(BT, 2, 2), 256, ATTN_SMEM_BYTES>>>();
    ln_kernel<<<dim3(BT, 16), 256>>>(gam, bet, y);
}

// round 5
// speedup vs baseline: 1.0732x; 1.0732x over previous
#include <cuda_runtime.h>
#include <math.h>

#define BB 8
#define CC 64
#define TT 24
#define NN 512
#define HH 2
#define HD 32
#define BT (BB*TT)

// ---------------- scratch (static device globals; no allocation) ----------------
__device__ float g_V[BT*NN*CC];      // V per (bt, n, c)
__device__ float g_O[BT*NN*CC];      // attention output pre-LN
__device__ float g_ssrc[BT*HH*NN];
__device__ float g_psrc[BT*HH*NN];
__device__ float g_qsrc[BT*HH*NN];
__device__ float g_sdst[BT*HH*NN];
__device__ float g_pdst[BT*HH*NN];
__device__ float g_qdst[BT*HH*NN];
__device__ float g_wqa[HH*CC];
__device__ float g_wka[HH*CC];
__device__ unsigned g_mask[NN*16];   // packed gso bits, row-major

// packed fp32x2 helpers (sm_103a FFMA2 — only reachable via PTX)
__device__ __forceinline__ void ffma2(unsigned long long& acc,
                                      unsigned long long a, unsigned long long b) {
    asm("fma.rn.f32x2 %0, %1, %2, %0;" : "+l"(acc) : "l"(a), "l"(b));
}
__device__ __forceinline__ unsigned long long pack2(float w) {
    unsigned long long r; unsigned u = __float_as_uint(w);
    asm("mov.b64 %0, {%1, %1};" : "=l"(r) : "r"(u));
    return r;
}
__device__ __forceinline__ float lo32(unsigned long long v) { return __uint_as_float((unsigned)v); }
__device__ __forceinline__ float hi32(unsigned long long v) { return __uint_as_float((unsigned)(v >> 32)); }

// ---------------- kernel A: fold a_src/a_dst into Wq/Wk; pack mask ----------------
__global__ void prep_kernel(const float* __restrict__ Wq, const float* __restrict__ Wk,
                            const float* __restrict__ a_src, const float* __restrict__ a_dst,
                            const int* __restrict__ gso) {
    int t = threadIdx.x;
    if (t < 128) {
        int h = t >> 6, c = t & 63;
        float s1 = 0.f, s2 = 0.f;
        for (int d = 0; d < HD; d++) {
            s1 += Wq[(h*HD + d)*CC + c] * a_src[h*HD + d];
            s2 += Wk[(h*HD + d)*CC + c] * a_dst[h*HD + d];
        }
        g_wqa[t] = s1;
        g_wka[t] = s2;
    }
    for (int w = t; w < NN*16; w += 256) {
        int r = w >> 4, wi = w & 15;
        const int* row = gso + r*NN + wi*32;
        unsigned bits = 0;
        #pragma unroll
        for (int b = 0; b < 32; b++) bits |= (row[b] != 0) ? (1u << b) : 0u;
        g_mask[w] = bits;
    }
}

// ---------------- kernel B: fused transpose + V projection + scores ----------------
__global__ __launch_bounds__(256) void qkv_kernel(const float* __restrict__ x,
                                                  const float* __restrict__ Wv) {
    __shared__ float sWv[CC*CC];
    __shared__ float swqa[HH*CC], swka[HH*CC];
    int tid = threadIdx.x;
    for (int e = tid; e < CC*CC; e += 256) sWv[e] = Wv[e];
    if (tid < 128) { swqa[tid] = g_wqa[tid]; swka[tid] = g_wka[tid]; }
    __syncthreads();

    int bt = blockIdx.x;
    int n  = blockIdx.y*256 + tid;
    int b = bt / TT, tim = bt % TT;
    const float* xp = x + (b*CC*TT + tim)*NN + n;   // + c*TT*NN strides

    float xv[CC];
    #pragma unroll
    for (int c = 0; c < CC; c++) xv[c] = xp[c*TT*NN];

    #pragma unroll
    for (int h = 0; h < HH; h++) {
        float s1 = 0.f, s2 = 0.f;
        #pragma unroll
        for (int c = 0; c < CC; c++) { s1 += xv[c]*swqa[h*CC+c]; s2 += xv[c]*swka[h*CC+c]; }
        int o = (bt*HH + h)*NN + n;
        g_ssrc[o] = s1; g_psrc[o] = expf(s1); g_qsrc[o] = expf(0.2f*s1);
        g_sdst[o] = s2; g_pdst[o] = expf(s2); g_qdst[o] = expf(0.2f*s2);
    }

    float* vp = g_V + (bt*NN + n)*CC;
    #pragma unroll
    for (int dg = 0; dg < 16; dg++) {
        float a0=0.f, a1=0.f, a2=0.f, a3=0.f;
        #pragma unroll
        for (int c = 0; c < CC; c++) {
            float xc = xv[c];
            a0 += xc*sWv[(dg*4+0)*CC + c];
            a1 += xc*sWv[(dg*4+1)*CC + c];
            a2 += xc*sWv[(dg*4+2)*CC + c];
            a3 += xc*sWv[(dg*4+3)*CC + c];
        }
        *(float4*)(vp + dg*4) = make_float4(a0, a1, a2, a3);
    }
}

// ---------------- kernel C: attention (W-tile build + f32x2 AV matmul) ----------------
// grid (bt=192, h=2, ihalf=2); block 256. Dynamic smem layout in floats:
#define OFF_V   0        // 512*32
#define OFF_W   16384    // 64*64  ([j][i])
#define OFF_SD  20480
#define OFF_PD  20992
#define OFF_QD  21504
#define OFF_SS  22016
#define OFF_PS  22272
#define OFF_QS  22528
#define OFF_ZP  22784    // 64*4
#define OFF_Z   23040    // 64
#define OFF_M   23104    // 256*17 uints (padded rows vs bank conflicts)
#define ATTN_SMEM_FLOATS (23104 + 256*17)
#define ATTN_SMEM_BYTES  (ATTN_SMEM_FLOATS*4)

__global__ __launch_bounds__(256) void attn_kernel() {
    extern __shared__ float sm[];
    float4*  sV4 = (float4*)sm;
    float*   sW  = sm + OFF_W;
    float*   sSd = sm + OFF_SD;
    float*   sPd = sm + OFF_PD;
    float*   sQd = sm + OFF_QD;
    float*   sSs = sm + OFF_SS;
    float*   sPs = sm + OFF_PS;
    float*   sQs = sm + OFF_QS;
    float*   sZp = sm + OFF_ZP;
    float*   sZ  = sm + OFF_Z;
    unsigned* sM = (unsigned*)(sm + OFF_M);

    int bt = blockIdx.x, h = blockIdx.y, ihalf = blockIdx.z;
    int tid = threadIdx.x;

    // load this head's V: [512][32] floats
    const float4* gV4 = (const float4*)(g_V + (bt*NN)*CC + h*HD);
    for (int e = tid; e < 4096; e += 256) {
        int j = e >> 3, q = e & 7;
        sV4[e] = gV4[j*16 + q];       // global row stride = 64 floats = 16 float4
    }
    int base = (bt*HH + h)*NN;
    for (int e = tid; e < NN; e += 256) {
        sSd[e] = g_sdst[base+e]; sPd[e] = g_pdst[base+e]; sQd[e] = g_qdst[base+e];
    }
    {
        int ib2 = base + ihalf*256;
        sSs[tid] = g_ssrc[ib2+tid]; sPs[tid] = g_psrc[ib2+tid]; sQs[tid] = g_qsrc[ib2+tid];
    }
    for (int e = tid; e < 4096; e += 256) {
        int r = e >> 4, wi = e & 15;
        sM[r*17 + wi] = g_mask[(ihalf*256 + r)*16 + wi];
    }
    __syncthreads();

    int warp = tid >> 5, lane = tid & 31;
    int i_sub = lane & 7, dq = lane >> 3;
    int iw = warp*8 + i_sub;             // matmul role: i within 64-block
    int bi = tid & 63, jc = tid >> 6;    // builder role

    for (int ib = 0; ib < 4; ib++) {
        float si = sSs[ib*64 + bi], pi = sPs[ib*64 + bi], qi = sQs[ib*64 + bi];
        int mrow = (ib*64 + bi)*17;
        float z = 0.f;
        unsigned long long a0 = 0ull, a1 = 0ull, a2 = 0ull, a3 = 0ull;

        for (int jt = 0; jt < 8; jt++) {
            // ---- build W tile [64 j][64 i] (each w computed exactly once) ----
            unsigned mword = sM[mrow + jt*2 + (jc >> 1)] >> ((jc & 1)*16);
            int jb = jt*64 + jc*16;
            float* wdst = sW + jc*16*64 + bi;
            #pragma unroll
            for (int cq = 0; cq < 4; cq++) {
                float4 sd = *(const float4*)(sSd + jb + cq*4);
                float4 pd = *(const float4*)(sPd + jb + cq*4);
                float4 qd = *(const float4*)(sQd + jb + cq*4);
                float w0 = (si + sd.x > 0.f) ? pi*pd.x : qi*qd.x;
                float w1 = (si + sd.y > 0.f) ? pi*pd.y : qi*qd.y;
                float w2 = (si + sd.z > 0.f) ? pi*pd.z : qi*qd.z;
                float w3 = (si + sd.w > 0.f) ? pi*pd.w : qi*qd.w;
                w0 = ((mword >> (cq*4+0)) & 1u) ? w0 : 0.f;
                w1 = ((mword >> (cq*4+1)) & 1u) ? w1 : 0.f;
                w2 = ((mword >> (cq*4+2)) & 1u) ? w2 : 0.f;
                w3 = ((mword >> (cq*4+3)) & 1u) ? w3 : 0.f;
                z += w0; z += w1; z += w2; z += w3;
                wdst[(cq*4+0)*64] = w0;          // coalesced STS across lanes
                wdst[(cq*4+1)*64] = w1;
                wdst[(cq*4+2)*64] = w2;
                wdst[(cq*4+3)*64] = w3;
            }
            __syncthreads();
            // ---- matmul: warp covers 8 i x 32 d; lane = (i_sub, dq) ----
            // packed f32x2 FMAs: 4 FFMA2 per j instead of 8 scalar FFMA
            const unsigned long long* vb =
                (const unsigned long long*)(sV4 + jt*64*8 + dq*2);
            const float* wb = sW + iw;
            #pragma unroll 16
            for (int j = 0; j < 64; j++) {
                unsigned long long w2p = pack2(wb[j*64]);   // 8 distinct scalars, multicast
                ulonglong2 p0 = *(const ulonglong2*)(vb + j*16);      // 16B
                ulonglong2 p1 = *(const ulonglong2*)(vb + j*16 + 2);  // 16B
                ffma2(a0, w2p, p0.x);
                ffma2(a1, w2p, p0.y);
                ffma2(a2, w2p, p1.x);
                ffma2(a3, w2p, p1.y);
            }
            __syncthreads();
        }
        // ---- softmax normalizer ----
        sZp[bi*4 + jc] = z;
        __syncthreads();
        if (tid < 64) sZ[tid] = sZp[tid*4] + sZp[tid*4+1] + sZp[tid*4+2] + sZp[tid*4+3];
        __syncthreads();
        float rz = 1.f / sZ[iw];
        int ig = ihalf*256 + ib*64 + iw;
        float* op = g_O + (bt*NN + ig)*CC + h*HD + dq*8;
        ((float4*)op)[0] = make_float4(lo32(a0)*rz, hi32(a0)*rz, lo32(a1)*rz, hi32(a1)*rz);
        ((float4*)op)[1] = make_float4(lo32(a2)*rz, hi32(a2)*rz, lo32(a3)*rz, hi32(a3)*rz);
        __syncthreads();
    }
}

// ---------------- kernel D: LayerNorm over C + transposed writeout ----------------
// 64 rows per block (float4 global loads, 4x the MLP of the old version)
__global__ __launch_bounds__(256) void ln_kernel(const float* __restrict__ gamma,
                                                 const float* __restrict__ beta,
                                                 float* __restrict__ y) {
    __shared__ float smb[64*65];
    __shared__ float sg[64], sb[64];
    int tid = threadIdx.x;
    int bt = blockIdx.x, nt = blockIdx.y;
    if (tid < 64) { sg[tid] = gamma[tid]; sb[tid] = beta[tid]; }
    const float4* o4 = (const float4*)(g_O + (bt*NN + nt*64)*CC);
    #pragma unroll
    for (int k = 0; k < 4; k++) {
        int e = tid + k*256;             // float4 index; row = e>>4, c = (e&15)*4
        float4 v = o4[e];
        float* d = &smb[(e >> 4)*65 + (e & 15)*4];
        d[0] = v.x; d[1] = v.y; d[2] = v.z; d[3] = v.w;
    }
    __syncthreads();

    int warp = tid >> 5, lane = tid & 31;
    #pragma unroll
    for (int k = 0; k < 8; k++) {
        int r = warp*8 + k;
        float v0 = smb[r*65 + lane], v1 = smb[r*65 + 32 + lane];
        float s = v0 + v1, ss2 = v0*v0 + v1*v1;
        #pragma unroll
        for (int off = 16; off; off >>= 1) {
            s   += __shfl_xor_sync(0xffffffffu, s, off);
            ss2 += __shfl_xor_sync(0xffffffffu, ss2, off);
        }
        float mu  = s*(1.f/64.f);
        float var = ss2*(1.f/64.f) - mu*mu;
        float rs  = rsqrtf(var + 1e-5f);
        smb[r*65 + lane]      = (v0 - mu)*rs*sg[lane]      + sb[lane];
        smb[r*65 + 32 + lane] = (v1 - mu)*rs*sg[32 + lane] + sb[32 + lane];
    }
    __syncthreads();

    int b = bt / TT, tim = bt % TT;
    int n = tid & 31, c0 = tid >> 5;
    #pragma unroll
    for (int nh = 0; nh < 2; nh++) {
        float* yp = y + (b*CC*TT + tim)*NN + nt*64 + nh*32 + n;
        #pragma unroll
        for (int k = 0; k < 8; k++) {
            int c = c0 + k*8;
            yp[c*TT*NN] = smb[(nh*32 + n)*65 + c];   // warp writes 32 consecutive n
        }
    }
}

// ---------------- launch ----------------
extern "C" void kernel_launch(void* const* d_in, const int* in_sizes, int n_in,
                              void* d_out, int out_size) {
    const float* x     = (const float*)d_in[0];
    const int*   gso   = (const int*)  d_in[1];
    const float* Wq    = (const float*)d_in[2];
    const float* Wk    = (const float*)d_in[3];
    const float* Wv    = (const float*)d_in[4];
    const float* a_src = (const float*)d_in[5];
    const float* a_dst = (const float*)d_in[6];
    const float* gam   = (const float*)d_in[7];
    const float* bet   = (const float*)d_in[8];
    float* y = (float*)d_out;

    cudaFuncSetAttribute(attn_kernel, cudaFuncAttributeMaxDynamicSharedMemorySize,
                         ATTN_SMEM_BYTES);

    prep_kernel<<<1, 256>>>(Wq, Wk, a_src, a_dst, gso);
    qkv_kernel<<<dim3(BT, 2), 256>>>(x, Wv);
    attn_kernel<<<dim3(BT, 2, 2), 256, ATTN_SMEM_BYTES>>>();
    ln_kernel<<<dim3(BT, 8), 256>>>(gam, bet, y);
}